// round 15
// baseline (speedup 1.0000x reference)
#include <cuda_runtime.h>
#include <cstdint>
#include <math.h>

// Problem constants
#define NN 32768
#define EE 8192
#define DD 128

// Scratch (static __device__ arrays — allocation-free per harness rules)
__device__ float g_dv[NN];        // node degrees
__device__ float g_de[EE];        // hyperedge degrees
__device__ float g_s[NN];         // dv_inv_sqrt (written by k_deg)
__device__ float g_m1[NN * DD];   // m1T [128 d][32768 n] = tf32(s .* x)^T
__device__ float g_m2[EE * DD];   // m2T [128 d][8192 e]  = m1T @ H ; then tf32(* dei)
__device__ float g_m4[NN * DD];   // m4  [32768 v][128 d] = H @ m3T^T

// ---------------------------------------------------------------------------
// helpers
// ---------------------------------------------------------------------------
__device__ __forceinline__ unsigned f2tf(float f) {
    unsigned u;
    asm("cvt.rna.tf32.f32 %0, %1;" : "=r"(u) : "f"(f));
    return u;
}

__device__ __forceinline__ void mma8(float* c, const unsigned* a, const unsigned* b) {
    asm volatile(
        "mma.sync.aligned.m16n8k8.row.col.f32.tf32.tf32.f32 "
        "{%0,%1,%2,%3}, {%4,%5,%6,%7}, {%8,%9}, {%0,%1,%2,%3};\n"
        : "+f"(c[0]), "+f"(c[1]), "+f"(c[2]), "+f"(c[3])
        : "r"(a[0]), "r"(a[1]), "r"(a[2]), "r"(a[3]), "r"(b[0]), "r"(b[1]));
}

__device__ __forceinline__ void cp16(unsigned dst, const void* src) {
    asm volatile("cp.async.cg.shared.global [%0], [%1], 16;\n" :: "r"(dst), "l"(src));
}
__device__ __forceinline__ void cp_commit() { asm volatile("cp.async.commit_group;\n"); }
template <int N>
__device__ __forceinline__ void cp_wait() {
    asm volatile("cp.async.wait_group %0;\n" :: "n"(N) : "memory");
}

// ldmatrix x4: four 8x8 b16 tiles == four 8x4 b32 tiles (tf32 fragments)
__device__ __forceinline__ void ldsm4(unsigned& r0, unsigned& r1, unsigned& r2,
                                      unsigned& r3, unsigned addr) {
    asm volatile("ldmatrix.sync.aligned.m8n8.x4.shared.b16 {%0,%1,%2,%3}, [%4];"
                 : "=r"(r0), "=r"(r1), "=r"(r2), "=r"(r3) : "r"(addr));
}

// ---------------------------------------------------------------------------
// Kernel 0: zero d_e and m2T (m2T receives split-K atomic adds)
// ---------------------------------------------------------------------------
__global__ void k_zero() {
    int i = blockIdx.x * 256 + threadIdx.x;
    float4 z = make_float4(0.f, 0.f, 0.f, 0.f);
    if (i < EE * DD / 4) reinterpret_cast<float4*>(g_m2)[i] = z;
    if (i < EE) g_de[i] = 0.0f;
}

// ---------------------------------------------------------------------------
// Kernel 1: one pass over H -> d_v (row sums, + g_s) and d_e (col sums).
// r15: re-gridded 256x128rows -> 1024x32rows. Inner loop identical to the
// r14-validated version; 4x less serial work per block, ~4x more resident
// CTAs chip-wide. d_e atomics grow to 8M spread-address REDG (~3us, noise).
// ---------------------------------------------------------------------------
#define DEG_ROWS 32
__global__ __launch_bounds__(256) void k_deg(const float* __restrict__ H) {
    __shared__ float rowacc[DEG_ROWS];
    const int t = threadIdx.x;
    if (t < DEG_ROWS) rowacc[t] = 0.0f;
    __syncthreads();

    const int r0 = blockIdx.x * DEG_ROWS;
    float col[32];
#pragma unroll
    for (int j = 0; j < 32; j++) col[j] = 0.0f;

    const float4* H4 = reinterpret_cast<const float4*>(H);
    for (int rb = 0; rb < DEG_ROWS; rb += 4) {
        float rs0 = 0.f, rs1 = 0.f, rs2 = 0.f, rs3 = 0.f;
#pragma unroll
        for (int rr = 0; rr < 4; rr++) {
            const float4* row = H4 + (size_t)(r0 + rb + rr) * (EE / 4);
            float rs = 0.0f;
#pragma unroll
            for (int j = 0; j < 8; j++) {
                float4 v = row[t * 8 + j];
                col[j * 4 + 0] += v.x;
                col[j * 4 + 1] += v.y;
                col[j * 4 + 2] += v.z;
                col[j * 4 + 3] += v.w;
                rs += (v.x + v.y) + (v.z + v.w);
            }
            if (rr == 0) rs0 = rs;
            else if (rr == 1) rs1 = rs;
            else if (rr == 2) rs2 = rs;
            else rs3 = rs;
        }
#pragma unroll
        for (int o = 16; o > 0; o >>= 1) {
            rs0 += __shfl_xor_sync(0xffffffffu, rs0, o);
            rs1 += __shfl_xor_sync(0xffffffffu, rs1, o);
            rs2 += __shfl_xor_sync(0xffffffffu, rs2, o);
            rs3 += __shfl_xor_sync(0xffffffffu, rs3, o);
        }
        if ((t & 31) == 0) {
            atomicAdd(&rowacc[rb + 0], rs0);
            atomicAdd(&rowacc[rb + 1], rs1);
            atomicAdd(&rowacc[rb + 2], rs2);
            atomicAdd(&rowacc[rb + 3], rs3);
        }
    }
    __syncthreads();
    if (t < DEG_ROWS) {
        float dv = rowacc[t];
        g_dv[r0 + t] = dv;
        g_s[r0 + t] = 1.0f / (sqrtf(dv) + 1e-8f);
    }

#pragma unroll
    for (int j = 0; j < 32; j++) atomicAdd(&g_de[t * 32 + j], col[j]);
}

// ---------------------------------------------------------------------------
// Kernel 2: m1T[d, n] = tf32(s[n] * x[n, d]) — tiled 32x32 transpose
// ---------------------------------------------------------------------------
__global__ __launch_bounds__(256) void k_m1t(const float* __restrict__ x) {
    __shared__ float tile[32][33];
    const int tx = threadIdx.x & 31, ty = threadIdx.x >> 5;
    const int n0 = blockIdx.x * 32, d0 = blockIdx.y * 32;
#pragma unroll
    for (int j = 0; j < 4; j++) {
        int n = n0 + ty + j * 8;
        tile[ty + j * 8][tx] = g_s[n] * x[(size_t)n * DD + d0 + tx];
    }
    __syncthreads();
#pragma unroll
    for (int j = 0; j < 4; j++) {
        int d = d0 + ty + j * 8;
        g_m1[(size_t)d * NN + n0 + tx] = __uint_as_float(f2tf(tile[tx][ty + j * 8]));
    }
}

// ---------------------------------------------------------------------------
// Kernel 4: m3T = tf32(m2T / (d_e[e]+eps)) (in place; e = fast dim of m2T)
// ---------------------------------------------------------------------------
__global__ void k_scale() {
    int i = blockIdx.x * 256 + threadIdx.x;
    if (i < EE * DD) {
        float dei = 1.0f / (g_de[i & (EE - 1)] + 1e-8f);
        g_m2[i] = __uint_as_float(f2tf(g_m2[i] * dei));
    }
}

// ---------------------------------------------------------------------------
// GEMM1: m2T[d, e-tile] += sum_n m1T[d, n] * H[n, e]   (r12-validated config)
//   A = m1T smem [m=d][36] (LDSM), B = H smem [k=n][136] (scalar .col frags)
//   Warp tile 32x64 (4m x 2n), 3-stage cp.async pipeline, wait_group 1.
// ---------------------------------------------------------------------------
__global__ __launch_bounds__(256, 2) void k_gemm1(const float* __restrict__ H,
                                                  const float* __restrict__ m1t,
                                                  float* __restrict__ m2t) {
    extern __shared__ __align__(16) float sm[];
    constexpr int ASZ = 128 * 36;   // 4608 floats
    constexpr int BSZ = 32 * 136;   // 4352 floats
    constexpr int STG = ASZ + BSZ;  // 8960 floats / stage (35840 B)

    const int t = threadIdx.x;
    const int lane = t & 31;
    const int w = t >> 5;
    const int wm = w & 3;
    const int wn = w >> 2;
    const int e0 = blockIdx.x * 128;
    const int kb = blockIdx.y * (NN / 4);
    const unsigned sbase = (unsigned)__cvta_generic_to_shared(sm);

    float acc[2][8][4];
#pragma unroll
    for (int mt = 0; mt < 2; mt++)
#pragma unroll
        for (int nt = 0; nt < 8; nt++)
#pragma unroll
            for (int i = 0; i < 4; i++) acc[mt][nt][i] = 0.0f;

    auto issue = [&](int kt) {
        const unsigned ab = sbase + (unsigned)((kt % 3) * STG) * 4u;
        const unsigned bb = ab + ASZ * 4u;
        const int n0 = kb + kt * 32;
#pragma unroll
        for (int i = 0; i < 4; i++) {            // A: 128 d-rows x 8 chunks
            int c = t + i * 256;
            int r = c >> 3, q = c & 7;
            cp16(ab + (unsigned)(r * 36 + q * 4) * 4u, m1t + (size_t)r * NN + n0 + q * 4);
        }
#pragma unroll
        for (int i = 0; i < 4; i++) {            // B: 32 n-rows x 32 chunks
            int c = t + i * 256;
            int r = c >> 5, q = c & 31;
            cp16(bb + (unsigned)(r * 136 + q * 4) * 4u,
                 H + (size_t)(n0 + r) * EE + e0 + q * 4);
        }
        cp_commit();
    };

    issue(0);
    issue(1);

    const int iters = (NN / 4) / 32;             // 256
    const int gid = lane >> 2, tig = lane & 3;
    const int lrow = lane & 7;
    const int lmh = (lane >> 3) & 1;             // +8 m-rows for matrices 1,3
    const int lkh = (lane >> 4) << 2;            // +4 k-cols for matrices 2,3

    for (int kt = 0; kt < iters; kt++) {
        cp_wait<1>();
        __syncthreads();
        if (kt + 2 < iters) issue(kt + 2);

        const unsigned ab = sbase + (unsigned)((kt % 3) * STG) * 4u;
        const float* bs = sm + (kt % 3) * STG + ASZ;
#pragma unroll
        for (int ks = 0; ks < 4; ks++) {
            const int kr = ks * 8;
            unsigned af[2][4];
#pragma unroll
            for (int mt = 0; mt < 2; mt++) {
                int m = wm * 32 + mt * 16 + lmh * 8 + lrow;
                ldsm4(af[mt][0], af[mt][1], af[mt][2], af[mt][3],
                      ab + (unsigned)(m * 36 + kr + lkh) * 4u);
            }
            unsigned bf[8][2];
#pragma unroll
            for (int nt = 0; nt < 8; nt++) {
                int bn = wn * 64 + nt * 8 + gid;
                bf[nt][0] = __float_as_uint(bs[(kr + tig) * 136 + bn]);
                bf[nt][1] = __float_as_uint(bs[(kr + tig + 4) * 136 + bn]);
            }
#pragma unroll
            for (int mt = 0; mt < 2; mt++)
#pragma unroll
                for (int nt = 0; nt < 8; nt++) mma8(acc[mt][nt], af[mt], bf[nt]);
        }
    }

    // Epilogue: D[m=d][n=e]; c0:(g,2t) c1:(g,2t+1) c2:(g+8,2t) c3:(g+8,2t+1)
#pragma unroll
    for (int mt = 0; mt < 2; mt++) {
#pragma unroll
        for (int nt = 0; nt < 8; nt++) {
            int d = wm * 32 + mt * 16 + gid;
            int e = e0 + wn * 64 + nt * 8 + 2 * tig;
            float* p = m2t + (size_t)d * EE + e;
            atomicAdd(p, acc[mt][nt][0]);
            atomicAdd(p + 1, acc[mt][nt][1]);
            atomicAdd(p + 8 * EE, acc[mt][nt][2]);
            atomicAdd(p + 8 * EE + 1, acc[mt][nt][3]);
        }
    }
}

// ---------------------------------------------------------------------------
// GEMM2: m4[v-tile, d] = sum_e H[v, e] * m3T[d, e]   (r12-validated config)
//   A = H smem [m=v][36] (LDSM), B = m3T smem [n=d][36] (LDSM).
//   Block tile 128x128, warp tile 32x64. 3-stage pipeline.
// ---------------------------------------------------------------------------
__global__ __launch_bounds__(256, 2) void k_gemm2(const float* __restrict__ H,
                                                  const float* __restrict__ m3t,
                                                  float* __restrict__ m4) {
    extern __shared__ __align__(16) float sm[];
    constexpr int ASZ = 128 * 36;
    constexpr int BSZ = 128 * 36;
    constexpr int STG = ASZ + BSZ;               // 9216 floats / stage (36864 B)

    const int t = threadIdx.x;
    const int lane = t & 31;
    const int w = t >> 5;
    const int wm = w & 3;
    const int wn = w >> 2;
    const int v0 = blockIdx.x * 128;
    const unsigned sbase = (unsigned)__cvta_generic_to_shared(sm);

    float acc[2][8][4];
#pragma unroll
    for (int mt = 0; mt < 2; mt++)
#pragma unroll
        for (int nt = 0; nt < 8; nt++)
#pragma unroll
            for (int i = 0; i < 4; i++) acc[mt][nt][i] = 0.0f;

    auto issue = [&](int kt) {
        const unsigned ab = sbase + (unsigned)((kt % 3) * STG) * 4u;
        const unsigned bb = ab + ASZ * 4u;
        const int ke = kt * 32;
#pragma unroll
        for (int i = 0; i < 4; i++) {            // A: H 128 v-rows x 8 chunks
            int c = t + i * 256;
            int r = c >> 3, q = c & 7;
            cp16(ab + (unsigned)(r * 36 + q * 4) * 4u,
                 H + (size_t)(v0 + r) * EE + ke + q * 4);
        }
#pragma unroll
        for (int i = 0; i < 4; i++) {            // B: m3T 128 d-rows x 8 chunks
            int c = t + i * 256;
            int r = c >> 3, q = c & 7;
            cp16(bb + (unsigned)(r * 36 + q * 4) * 4u,
                 m3t + (size_t)r * EE + ke + q * 4);
        }
        cp_commit();
    };

    issue(0);
    issue(1);

    const int iters = EE / 32;                    // 256
    const int gid = lane >> 2, tig = lane & 3;
    const int lrow = lane & 7;
    const int lmh = (lane >> 3) & 1;
    const int lkh = (lane >> 4) << 2;
    const int bnh = (lane >> 4) << 3;             // +8 n-rows for matrices 2,3
    const int bkh = ((lane >> 3) & 1) << 2;       // +4 k-cols for matrices 1,3

    for (int kt = 0; kt < iters; kt++) {
        cp_wait<1>();
        __syncthreads();
        if (kt + 2 < iters) issue(kt + 2);

        const unsigned ab = sbase + (unsigned)((kt % 3) * STG) * 4u;
        const unsigned bb = ab + ASZ * 4u;
#pragma unroll
        for (int ks = 0; ks < 4; ks++) {
            const int kr = ks * 8;
            unsigned af[2][4];
#pragma unroll
            for (int mt = 0; mt < 2; mt++) {
                int m = wm * 32 + mt * 16 + lmh * 8 + lrow;
                ldsm4(af[mt][0], af[mt][1], af[mt][2], af[mt][3],
                      ab + (unsigned)(m * 36 + kr + lkh) * 4u);
            }
            unsigned bf[8][2];
#pragma unroll
            for (int p = 0; p < 4; p++) {
                int n = wn * 64 + p * 16 + bnh + lrow;
                unsigned r0, r1, r2, r3;
                ldsm4(r0, r1, r2, r3, bb + (unsigned)(n * 36 + kr + bkh) * 4u);
                bf[2 * p][0] = r0;
                bf[2 * p][1] = r1;
                bf[2 * p + 1][0] = r2;
                bf[2 * p + 1][1] = r3;
            }
#pragma unroll
            for (int mt = 0; mt < 2; mt++)
#pragma unroll
                for (int nt = 0; nt < 8; nt++) mma8(acc[mt][nt], af[mt], bf[nt]);
        }
    }

    // Epilogue: D[m=v][n=d] plain store
#pragma unroll
    for (int mt = 0; mt < 2; mt++) {
#pragma unroll
        for (int nt = 0; nt < 8; nt++) {
            int m = v0 + wm * 32 + mt * 16 + gid;
            int n = wn * 64 + nt * 8 + 2 * tig;
            float* p = m4 + (size_t)m * DD + n;
            p[0] = acc[mt][nt][0];
            p[1] = acc[mt][nt][1];
            p[8 * DD] = acc[mt][nt][2];
            p[8 * DD + 1] = acc[mt][nt][3];
        }
    }
}

// ---------------------------------------------------------------------------
// Kernel 6: per row n:  v = s[n]*m4[n,:];  h = W@v + b;  relu;  layernorm.
// ---------------------------------------------------------------------------
__global__ __launch_bounds__(256) void k_final(const float* __restrict__ W,
                                               const float* __restrict__ bias,
                                               const float* __restrict__ gamma,
                                               const float* __restrict__ beta,
                                               float* __restrict__ out) {
    __shared__ float vbuf[8][132];
    const int t = threadIdx.x;
    const int lane = t & 31;
    const int w = t >> 5;

    const float4 bb = *reinterpret_cast<const float4*>(bias + 4 * lane);
    const float4 gg = *reinterpret_cast<const float4*>(gamma + 4 * lane);
    const float4 eb = *reinterpret_cast<const float4*>(beta + 4 * lane);
    const float4* W4 = reinterpret_cast<const float4*>(W);

    for (int n = blockIdx.x * 8 + w; n < NN; n += gridDim.x * 8) {
        const float s = g_s[n];
        float4 mv = *reinterpret_cast<const float4*>(g_m4 + (size_t)n * DD + 4 * lane);
        vbuf[w][4 * lane + 0] = s * mv.x;
        vbuf[w][4 * lane + 1] = s * mv.y;
        vbuf[w][4 * lane + 2] = s * mv.z;
        vbuf[w][4 * lane + 3] = s * mv.w;
        __syncwarp();

        float h0 = bb.x, h1 = bb.y, h2 = bb.z, h3 = bb.w;
#pragma unroll 8
        for (int dq = 0; dq < 32; dq++) {
            float4 v4 = *reinterpret_cast<float4*>(&vbuf[w][dq * 4]);
            float4 w0 = W4[(4 * lane + 0) * 32 + dq];
            float4 w1 = W4[(4 * lane + 1) * 32 + dq];
            float4 w2 = W4[(4 * lane + 2) * 32 + dq];
            float4 w3 = W4[(4 * lane + 3) * 32 + dq];
            h0 += w0.x * v4.x + w0.y * v4.y + w0.z * v4.z + w0.w * v4.w;
            h1 += w1.x * v4.x + w1.y * v4.y + w1.z * v4.z + w1.w * v4.w;
            h2 += w2.x * v4.x + w2.y * v4.y + w2.z * v4.z + w2.w * v4.w;
            h3 += w3.x * v4.x + w3.y * v4.y + w3.z * v4.z + w3.w * v4.w;
        }
        h0 = fmaxf(h0, 0.0f);
        h1 = fmaxf(h1, 0.0f);
        h2 = fmaxf(h2, 0.0f);
        h3 = fmaxf(h3, 0.0f);

        float sum = h0 + h1 + h2 + h3;
#pragma unroll
        for (int o = 16; o > 0; o >>= 1) sum += __shfl_xor_sync(0xffffffffu, sum, o);
        const float mu = sum * (1.0f / 128.0f);
        const float d0 = h0 - mu, d1 = h1 - mu, d2 = h2 - mu, d3 = h3 - mu;
        float vs = d0 * d0 + d1 * d1 + d2 * d2 + d3 * d3;
#pragma unroll
        for (int o = 16; o > 0; o >>= 1) vs += __shfl_xor_sync(0xffffffffu, vs, o);
        const float inv = rsqrtf(vs * (1.0f / 128.0f) + 1e-5f);

        float4 o4;
        o4.x = gg.x * d0 * inv + eb.x;
        o4.y = gg.y * d1 * inv + eb.y;
        o4.z = gg.z * d2 * inv + eb.z;
        o4.w = gg.w * d3 * inv + eb.w;
        *reinterpret_cast<float4*>(out + (size_t)n * DD + 4 * lane) = o4;
        __syncwarp();
    }
}

// ---------------------------------------------------------------------------
// Launch
// ---------------------------------------------------------------------------
extern "C" void kernel_launch(void* const* d_in, const int* in_sizes, int n_in,
                              void* d_out, int out_size) {
    const float* x     = (const float*)d_in[0];   // (N, 128)
    const float* H     = (const float*)d_in[1];   // (N, E)
    const float* W     = (const float*)d_in[2];   // (128, 128)
    const float* bias  = (const float*)d_in[3];   // (128,)
    const float* gamma = (const float*)d_in[4];   // (128,)
    const float* beta  = (const float*)d_in[5];   // (128,)
    float* out = (float*)d_out;

    // Resolve true device addresses of scratch symbols (round-8 fix).
    float *p_m1 = nullptr, *p_m2 = nullptr, *p_m4 = nullptr;
    cudaGetSymbolAddress((void**)&p_m1, g_m1);
    cudaGetSymbolAddress((void**)&p_m2, g_m2);
    cudaGetSymbolAddress((void**)&p_m4, g_m4);

    constexpr int SMEM_G1 = 3 * (128 * 36 + 32 * 136) * 4;   // 107520 B
    constexpr int SMEM_G2 = 3 * (128 * 36 + 128 * 36) * 4;   // 110592 B
    cudaFuncSetAttribute(k_gemm1, cudaFuncAttributeMaxDynamicSharedMemorySize, SMEM_G1);
    cudaFuncSetAttribute(k_gemm2, cudaFuncAttributeMaxDynamicSharedMemorySize, SMEM_G2);

    // 0. zero d_e + m2T (split-K accumulator)
    k_zero<<<(EE * DD / 4 + 255) / 256, 256>>>();
    // 1. degrees (single pass over H); also writes g_s. r15: 1024 blocks.
    k_deg<<<NN / DEG_ROWS, 256>>>(H);
    // 2. m1T = tf32(s .* x)^T
    k_m1t<<<dim3(NN / 32, DD / 32), 256>>>(x);
    // 3. GEMM1: m2T += m1T @ H   (split-K=4, atomic)  <- profiled launch
    k_gemm1<<<dim3(EE / 128, 4), 256, SMEM_G1>>>(H, p_m1, p_m2);
    // 4. m3T = tf32(m2T / (d_e+eps)) (in place)
    k_scale<<<(EE * DD) / 256, 256>>>();
    // 5. GEMM2: m4 = H @ m3T^T
    k_gemm2<<<NN / 128, 256, SMEM_G2>>>(H, p_m2, p_m4);
    // 6. linear + relu + layernorm
    k_final<<<256, 256>>>(W, bias, gamma, beta, out);
}

// round 16
// speedup vs baseline: 1.1007x; 1.1007x over previous
#include <cuda_runtime.h>
#include <cstdint>
#include <math.h>

// Problem constants
#define NN 32768
#define EE 8192
#define DD 128

// Scratch (static __device__ arrays — allocation-free per harness rules)
__device__ float g_dv[NN];        // node degrees
__device__ float g_de[EE];        // hyperedge degrees
__device__ float g_s[NN];         // dv_inv_sqrt (written by k_deg)
__device__ float g_m1[NN * DD];   // m1T [128 d][32768 n] = tf32(s .* x)^T
__device__ float g_m2[EE * DD];   // m2T [128 d][8192 e]  = m1T @ H ; then tf32(* dei)
__device__ float g_m4[NN * DD];   // m4  [32768 v][128 d] = H @ m3T^T

// ---------------------------------------------------------------------------
// helpers
// ---------------------------------------------------------------------------
__device__ __forceinline__ unsigned f2tf(float f) {
    unsigned u;
    asm("cvt.rna.tf32.f32 %0, %1;" : "=r"(u) : "f"(f));
    return u;
}

__device__ __forceinline__ void mma8(float* c, const unsigned* a, const unsigned* b) {
    asm volatile(
        "mma.sync.aligned.m16n8k8.row.col.f32.tf32.tf32.f32 "
        "{%0,%1,%2,%3}, {%4,%5,%6,%7}, {%8,%9}, {%0,%1,%2,%3};\n"
        : "+f"(c[0]), "+f"(c[1]), "+f"(c[2]), "+f"(c[3])
        : "r"(a[0]), "r"(a[1]), "r"(a[2]), "r"(a[3]), "r"(b[0]), "r"(b[1]));
}

__device__ __forceinline__ void cp16(unsigned dst, const void* src) {
    asm volatile("cp.async.cg.shared.global [%0], [%1], 16;\n" :: "r"(dst), "l"(src));
}
__device__ __forceinline__ void cp_commit() { asm volatile("cp.async.commit_group;\n"); }
template <int N>
__device__ __forceinline__ void cp_wait() {
    asm volatile("cp.async.wait_group %0;\n" :: "n"(N) : "memory");
}

// ldmatrix x4: four 8x8 b16 tiles == four 8x4 b32 tiles (tf32 fragments)
__device__ __forceinline__ void ldsm4(unsigned& r0, unsigned& r1, unsigned& r2,
                                      unsigned& r3, unsigned addr) {
    asm volatile("ldmatrix.sync.aligned.m8n8.x4.shared.b16 {%0,%1,%2,%3}, [%4];"
                 : "=r"(r0), "=r"(r1), "=r"(r2), "=r"(r3) : "r"(addr));
}

// ---------------------------------------------------------------------------
// Kernel 0: zero d_e and m2T (m2T receives split-K atomic adds)
// ---------------------------------------------------------------------------
__global__ void k_zero() {
    int i = blockIdx.x * 256 + threadIdx.x;
    float4 z = make_float4(0.f, 0.f, 0.f, 0.f);
    if (i < EE * DD / 4) reinterpret_cast<float4*>(g_m2)[i] = z;
    if (i < EE) g_de[i] = 0.0f;
}

// ---------------------------------------------------------------------------
// Kernel 1: one pass over H -> d_v (row sums, + g_s) and d_e (col sums).
// r16 FIX: coalesced addressing. Thread t reads float4 idx j*256+t, so a
// warp's LDG.128 covers 4 full 128B lines (4 wavefronts, the floor) instead
// of 32 lines x 1 sector (32 wavefronts) as in r9..r15. Column ownership
// remaps to cols 4*(j*256+t)+c; row sums become 8 per-warp partials merged
// through the existing smem atomicAdd. 256 blocks x 128 rows, 2M d_e atomics.
// ---------------------------------------------------------------------------
#define DEG_ROWS 128
__global__ __launch_bounds__(256) void k_deg(const float* __restrict__ H) {
    __shared__ float rowacc[DEG_ROWS];
    const int t = threadIdx.x;
    if (t < DEG_ROWS) rowacc[t] = 0.0f;
    __syncthreads();

    const int r0 = blockIdx.x * DEG_ROWS;
    float col[32];
#pragma unroll
    for (int j = 0; j < 32; j++) col[j] = 0.0f;

    const float4* H4 = reinterpret_cast<const float4*>(H);
    for (int rb = 0; rb < DEG_ROWS; rb += 4) {
        float rs0 = 0.f, rs1 = 0.f, rs2 = 0.f, rs3 = 0.f;
#pragma unroll
        for (int rr = 0; rr < 4; rr++) {
            const float4* row = H4 + (size_t)(r0 + rb + rr) * (EE / 4);
            float rs = 0.0f;
#pragma unroll
            for (int j = 0; j < 8; j++) {
                float4 v = row[j * 256 + t];          // coalesced across lanes
                col[j * 4 + 0] += v.x;
                col[j * 4 + 1] += v.y;
                col[j * 4 + 2] += v.z;
                col[j * 4 + 3] += v.w;
                rs += (v.x + v.y) + (v.z + v.w);
            }
            if (rr == 0) rs0 = rs;
            else if (rr == 1) rs1 = rs;
            else if (rr == 2) rs2 = rs;
            else rs3 = rs;
        }
#pragma unroll
        for (int o = 16; o > 0; o >>= 1) {
            rs0 += __shfl_xor_sync(0xffffffffu, rs0, o);
            rs1 += __shfl_xor_sync(0xffffffffu, rs1, o);
            rs2 += __shfl_xor_sync(0xffffffffu, rs2, o);
            rs3 += __shfl_xor_sync(0xffffffffu, rs3, o);
        }
        if ((t & 31) == 0) {                          // 8 warp-partials per row
            atomicAdd(&rowacc[rb + 0], rs0);
            atomicAdd(&rowacc[rb + 1], rs1);
            atomicAdd(&rowacc[rb + 2], rs2);
            atomicAdd(&rowacc[rb + 3], rs3);
        }
    }
    __syncthreads();
    if (t < DEG_ROWS) {
        float dv = rowacc[t];
        g_dv[r0 + t] = dv;
        g_s[r0 + t] = 1.0f / (sqrtf(dv) + 1e-8f);
    }

#pragma unroll
    for (int j = 0; j < 8; j++) {
#pragma unroll
        for (int c = 0; c < 4; c++)
            atomicAdd(&g_de[(j * 256 + t) * 4 + c], col[j * 4 + c]);
    }
}

// ---------------------------------------------------------------------------
// Kernel 2: m1T[d, n] = tf32(s[n] * x[n, d]) — tiled 32x32 transpose
// ---------------------------------------------------------------------------
__global__ __launch_bounds__(256) void k_m1t(const float* __restrict__ x) {
    __shared__ float tile[32][33];
    const int tx = threadIdx.x & 31, ty = threadIdx.x >> 5;
    const int n0 = blockIdx.x * 32, d0 = blockIdx.y * 32;
#pragma unroll
    for (int j = 0; j < 4; j++) {
        int n = n0 + ty + j * 8;
        tile[ty + j * 8][tx] = g_s[n] * x[(size_t)n * DD + d0 + tx];
    }
    __syncthreads();
#pragma unroll
    for (int j = 0; j < 4; j++) {
        int d = d0 + ty + j * 8;
        g_m1[(size_t)d * NN + n0 + tx] = __uint_as_float(f2tf(tile[tx][ty + j * 8]));
    }
}

// ---------------------------------------------------------------------------
// Kernel 4: m3T = tf32(m2T / (d_e[e]+eps)) (in place; e = fast dim of m2T)
// ---------------------------------------------------------------------------
__global__ void k_scale() {
    int i = blockIdx.x * 256 + threadIdx.x;
    if (i < EE * DD) {
        float dei = 1.0f / (g_de[i & (EE - 1)] + 1e-8f);
        g_m2[i] = __uint_as_float(f2tf(g_m2[i] * dei));
    }
}

// ---------------------------------------------------------------------------
// GEMM1: m2T[d, e-tile] += sum_n m1T[d, n] * H[n, e]   (r12-validated config)
//   A = m1T smem [m=d][36] (LDSM), B = H smem [k=n][136] (scalar .col frags)
//   Warp tile 32x64 (4m x 2n), 3-stage cp.async pipeline, wait_group 1.
// ---------------------------------------------------------------------------
__global__ __launch_bounds__(256, 2) void k_gemm1(const float* __restrict__ H,
                                                  const float* __restrict__ m1t,
                                                  float* __restrict__ m2t) {
    extern __shared__ __align__(16) float sm[];
    constexpr int ASZ = 128 * 36;   // 4608 floats
    constexpr int BSZ = 32 * 136;   // 4352 floats
    constexpr int STG = ASZ + BSZ;  // 8960 floats / stage (35840 B)

    const int t = threadIdx.x;
    const int lane = t & 31;
    const int w = t >> 5;
    const int wm = w & 3;
    const int wn = w >> 2;
    const int e0 = blockIdx.x * 128;
    const int kb = blockIdx.y * (NN / 4);
    const unsigned sbase = (unsigned)__cvta_generic_to_shared(sm);

    float acc[2][8][4];
#pragma unroll
    for (int mt = 0; mt < 2; mt++)
#pragma unroll
        for (int nt = 0; nt < 8; nt++)
#pragma unroll
            for (int i = 0; i < 4; i++) acc[mt][nt][i] = 0.0f;

    auto issue = [&](int kt) {
        const unsigned ab = sbase + (unsigned)((kt % 3) * STG) * 4u;
        const unsigned bb = ab + ASZ * 4u;
        const int n0 = kb + kt * 32;
#pragma unroll
        for (int i = 0; i < 4; i++) {            // A: 128 d-rows x 8 chunks
            int c = t + i * 256;
            int r = c >> 3, q = c & 7;
            cp16(ab + (unsigned)(r * 36 + q * 4) * 4u, m1t + (size_t)r * NN + n0 + q * 4);
        }
#pragma unroll
        for (int i = 0; i < 4; i++) {            // B: 32 n-rows x 32 chunks
            int c = t + i * 256;
            int r = c >> 5, q = c & 31;
            cp16(bb + (unsigned)(r * 136 + q * 4) * 4u,
                 H + (size_t)(n0 + r) * EE + e0 + q * 4);
        }
        cp_commit();
    };

    issue(0);
    issue(1);

    const int iters = (NN / 4) / 32;             // 256
    const int gid = lane >> 2, tig = lane & 3;
    const int lrow = lane & 7;
    const int lmh = (lane >> 3) & 1;             // +8 m-rows for matrices 1,3
    const int lkh = (lane >> 4) << 2;            // +4 k-cols for matrices 2,3

    for (int kt = 0; kt < iters; kt++) {
        cp_wait<1>();
        __syncthreads();
        if (kt + 2 < iters) issue(kt + 2);

        const unsigned ab = sbase + (unsigned)((kt % 3) * STG) * 4u;
        const float* bs = sm + (kt % 3) * STG + ASZ;
#pragma unroll
        for (int ks = 0; ks < 4; ks++) {
            const int kr = ks * 8;
            unsigned af[2][4];
#pragma unroll
            for (int mt = 0; mt < 2; mt++) {
                int m = wm * 32 + mt * 16 + lmh * 8 + lrow;
                ldsm4(af[mt][0], af[mt][1], af[mt][2], af[mt][3],
                      ab + (unsigned)(m * 36 + kr + lkh) * 4u);
            }
            unsigned bf[8][2];
#pragma unroll
            for (int nt = 0; nt < 8; nt++) {
                int bn = wn * 64 + nt * 8 + gid;
                bf[nt][0] = __float_as_uint(bs[(kr + tig) * 136 + bn]);
                bf[nt][1] = __float_as_uint(bs[(kr + tig + 4) * 136 + bn]);
            }
#pragma unroll
            for (int mt = 0; mt < 2; mt++)
#pragma unroll
                for (int nt = 0; nt < 8; nt++) mma8(acc[mt][nt], af[mt], bf[nt]);
        }
    }

    // Epilogue: D[m=d][n=e]; c0:(g,2t) c1:(g,2t+1) c2:(g+8,2t) c3:(g+8,2t+1)
#pragma unroll
    for (int mt = 0; mt < 2; mt++) {
#pragma unroll
        for (int nt = 0; nt < 8; nt++) {
            int d = wm * 32 + mt * 16 + gid;
            int e = e0 + wn * 64 + nt * 8 + 2 * tig;
            float* p = m2t + (size_t)d * EE + e;
            atomicAdd(p, acc[mt][nt][0]);
            atomicAdd(p + 1, acc[mt][nt][1]);
            atomicAdd(p + 8 * EE, acc[mt][nt][2]);
            atomicAdd(p + 8 * EE + 1, acc[mt][nt][3]);
        }
    }
}

// ---------------------------------------------------------------------------
// GEMM2: m4[v-tile, d] = sum_e H[v, e] * m3T[d, e]   (r12-validated config)
//   A = H smem [m=v][36] (LDSM), B = m3T smem [n=d][36] (LDSM).
//   Block tile 128x128, warp tile 32x64. 3-stage pipeline.
// ---------------------------------------------------------------------------
__global__ __launch_bounds__(256, 2) void k_gemm2(const float* __restrict__ H,
                                                  const float* __restrict__ m3t,
                                                  float* __restrict__ m4) {
    extern __shared__ __align__(16) float sm[];
    constexpr int ASZ = 128 * 36;
    constexpr int BSZ = 128 * 36;
    constexpr int STG = ASZ + BSZ;               // 9216 floats / stage (36864 B)

    const int t = threadIdx.x;
    const int lane = t & 31;
    const int w = t >> 5;
    const int wm = w & 3;
    const int wn = w >> 2;
    const int v0 = blockIdx.x * 128;
    const unsigned sbase = (unsigned)__cvta_generic_to_shared(sm);

    float acc[2][8][4];
#pragma unroll
    for (int mt = 0; mt < 2; mt++)
#pragma unroll
        for (int nt = 0; nt < 8; nt++)
#pragma unroll
            for (int i = 0; i < 4; i++) acc[mt][nt][i] = 0.0f;

    auto issue = [&](int kt) {
        const unsigned ab = sbase + (unsigned)((kt % 3) * STG) * 4u;
        const unsigned bb = ab + ASZ * 4u;
        const int ke = kt * 32;
#pragma unroll
        for (int i = 0; i < 4; i++) {            // A: H 128 v-rows x 8 chunks
            int c = t + i * 256;
            int r = c >> 3, q = c & 7;
            cp16(ab + (unsigned)(r * 36 + q * 4) * 4u,
                 H + (size_t)(v0 + r) * EE + ke + q * 4);
        }
#pragma unroll
        for (int i = 0; i < 4; i++) {            // B: m3T 128 d-rows x 8 chunks
            int c = t + i * 256;
            int r = c >> 3, q = c & 7;
            cp16(bb + (unsigned)(r * 36 + q * 4) * 4u,
                 m3t + (size_t)r * EE + ke + q * 4);
        }
        cp_commit();
    };

    issue(0);
    issue(1);

    const int iters = EE / 32;                    // 256
    const int gid = lane >> 2, tig = lane & 3;
    const int lrow = lane & 7;
    const int lmh = (lane >> 3) & 1;
    const int lkh = (lane >> 4) << 2;
    const int bnh = (lane >> 4) << 3;             // +8 n-rows for matrices 2,3
    const int bkh = ((lane >> 3) & 1) << 2;       // +4 k-cols for matrices 1,3

    for (int kt = 0; kt < iters; kt++) {
        cp_wait<1>();
        __syncthreads();
        if (kt + 2 < iters) issue(kt + 2);

        const unsigned ab = sbase + (unsigned)((kt % 3) * STG) * 4u;
        const unsigned bb = ab + ASZ * 4u;
#pragma unroll
        for (int ks = 0; ks < 4; ks++) {
            const int kr = ks * 8;
            unsigned af[2][4];
#pragma unroll
            for (int mt = 0; mt < 2; mt++) {
                int m = wm * 32 + mt * 16 + lmh * 8 + lrow;
                ldsm4(af[mt][0], af[mt][1], af[mt][2], af[mt][3],
                      ab + (unsigned)(m * 36 + kr + lkh) * 4u);
            }
            unsigned bf[8][2];
#pragma unroll
            for (int p = 0; p < 4; p++) {
                int n = wn * 64 + p * 16 + bnh + lrow;
                unsigned r0, r1, r2, r3;
                ldsm4(r0, r1, r2, r3, bb + (unsigned)(n * 36 + kr + bkh) * 4u);
                bf[2 * p][0] = r0;
                bf[2 * p][1] = r1;
                bf[2 * p + 1][0] = r2;
                bf[2 * p + 1][1] = r3;
            }
#pragma unroll
            for (int mt = 0; mt < 2; mt++)
#pragma unroll
                for (int nt = 0; nt < 8; nt++) mma8(acc[mt][nt], af[mt], bf[nt]);
        }
    }

    // Epilogue: D[m=v][n=d] plain store
#pragma unroll
    for (int mt = 0; mt < 2; mt++) {
#pragma unroll
        for (int nt = 0; nt < 8; nt++) {
            int m = v0 + wm * 32 + mt * 16 + gid;
            int n = wn * 64 + nt * 8 + 2 * tig;
            float* p = m4 + (size_t)m * DD + n;
            p[0] = acc[mt][nt][0];
            p[1] = acc[mt][nt][1];
            p[8 * DD] = acc[mt][nt][2];
            p[8 * DD + 1] = acc[mt][nt][3];
        }
    }
}

// ---------------------------------------------------------------------------
// Kernel 6: per row n:  v = s[n]*m4[n,:];  h = W@v + b;  relu;  layernorm.
// ---------------------------------------------------------------------------
__global__ __launch_bounds__(256) void k_final(const float* __restrict__ W,
                                               const float* __restrict__ bias,
                                               const float* __restrict__ gamma,
                                               const float* __restrict__ beta,
                                               float* __restrict__ out) {
    __shared__ float vbuf[8][132];
    const int t = threadIdx.x;
    const int lane = t & 31;
    const int w = t >> 5;

    const float4 bb = *reinterpret_cast<const float4*>(bias + 4 * lane);
    const float4 gg = *reinterpret_cast<const float4*>(gamma + 4 * lane);
    const float4 eb = *reinterpret_cast<const float4*>(beta + 4 * lane);
    const float4* W4 = reinterpret_cast<const float4*>(W);

    for (int n = blockIdx.x * 8 + w; n < NN; n += gridDim.x * 8) {
        const float s = g_s[n];
        float4 mv = *reinterpret_cast<const float4*>(g_m4 + (size_t)n * DD + 4 * lane);
        vbuf[w][4 * lane + 0] = s * mv.x;
        vbuf[w][4 * lane + 1] = s * mv.y;
        vbuf[w][4 * lane + 2] = s * mv.z;
        vbuf[w][4 * lane + 3] = s * mv.w;
        __syncwarp();

        float h0 = bb.x, h1 = bb.y, h2 = bb.z, h3 = bb.w;
#pragma unroll 8
        for (int dq = 0; dq < 32; dq++) {
            float4 v4 = *reinterpret_cast<float4*>(&vbuf[w][dq * 4]);
            float4 w0 = W4[(4 * lane + 0) * 32 + dq];
            float4 w1 = W4[(4 * lane + 1) * 32 + dq];
            float4 w2 = W4[(4 * lane + 2) * 32 + dq];
            float4 w3 = W4[(4 * lane + 3) * 32 + dq];
            h0 += w0.x * v4.x + w0.y * v4.y + w0.z * v4.z + w0.w * v4.w;
            h1 += w1.x * v4.x + w1.y * v4.y + w1.z * v4.z + w1.w * v4.w;
            h2 += w2.x * v4.x + w2.y * v4.y + w2.z * v4.z + w2.w * v4.w;
            h3 += w3.x * v4.x + w3.y * v4.y + w3.z * v4.z + w3.w * v4.w;
        }
        h0 = fmaxf(h0, 0.0f);
        h1 = fmaxf(h1, 0.0f);
        h2 = fmaxf(h2, 0.0f);
        h3 = fmaxf(h3, 0.0f);

        float sum = h0 + h1 + h2 + h3;
#pragma unroll
        for (int o = 16; o > 0; o >>= 1) sum += __shfl_xor_sync(0xffffffffu, sum, o);
        const float mu = sum * (1.0f / 128.0f);
        const float d0 = h0 - mu, d1 = h1 - mu, d2 = h2 - mu, d3 = h3 - mu;
        float vs = d0 * d0 + d1 * d1 + d2 * d2 + d3 * d3;
#pragma unroll
        for (int o = 16; o > 0; o >>= 1) vs += __shfl_xor_sync(0xffffffffu, vs, o);
        const float inv = rsqrtf(vs * (1.0f / 128.0f) + 1e-5f);

        float4 o4;
        o4.x = gg.x * d0 * inv + eb.x;
        o4.y = gg.y * d1 * inv + eb.y;
        o4.z = gg.z * d2 * inv + eb.z;
        o4.w = gg.w * d3 * inv + eb.w;
        *reinterpret_cast<float4*>(out + (size_t)n * DD + 4 * lane) = o4;
        __syncwarp();
    }
}

// ---------------------------------------------------------------------------
// Launch
// ---------------------------------------------------------------------------
extern "C" void kernel_launch(void* const* d_in, const int* in_sizes, int n_in,
                              void* d_out, int out_size) {
    const float* x     = (const float*)d_in[0];   // (N, 128)
    const float* H     = (const float*)d_in[1];   // (N, E)
    const float* W     = (const float*)d_in[2];   // (128, 128)
    const float* bias  = (const float*)d_in[3];   // (128,)
    const float* gamma = (const float*)d_in[4];   // (128,)
    const float* beta  = (const float*)d_in[5];   // (128,)
    float* out = (float*)d_out;

    // Resolve true device addresses of scratch symbols (round-8 fix).
    float *p_m1 = nullptr, *p_m2 = nullptr, *p_m4 = nullptr;
    cudaGetSymbolAddress((void**)&p_m1, g_m1);
    cudaGetSymbolAddress((void**)&p_m2, g_m2);
    cudaGetSymbolAddress((void**)&p_m4, g_m4);

    constexpr int SMEM_G1 = 3 * (128 * 36 + 32 * 136) * 4;   // 107520 B
    constexpr int SMEM_G2 = 3 * (128 * 36 + 128 * 36) * 4;   // 110592 B
    cudaFuncSetAttribute(k_gemm1, cudaFuncAttributeMaxDynamicSharedMemorySize, SMEM_G1);
    cudaFuncSetAttribute(k_gemm2, cudaFuncAttributeMaxDynamicSharedMemorySize, SMEM_G2);

    // 0. zero d_e + m2T (split-K accumulator)
    k_zero<<<(EE * DD / 4 + 255) / 256, 256>>>();
    // 1. degrees (single coalesced pass over H); also writes g_s
    k_deg<<<NN / DEG_ROWS, 256>>>(H);
    // 2. m1T = tf32(s .* x)^T
    k_m1t<<<dim3(NN / 32, DD / 32), 256>>>(x);
    // 3. GEMM1: m2T += m1T @ H   (split-K=4, atomic)  <- profiled launch
    k_gemm1<<<dim3(EE / 128, 4), 256, SMEM_G1>>>(H, p_m1, p_m2);
    // 4. m3T = tf32(m2T / (d_e+eps)) (in place)
    k_scale<<<(EE * DD) / 256, 256>>>();
    // 5. GEMM2: m4 = H @ m3T^T
    k_gemm2<<<NN / 128, 256, SMEM_G2>>>(H, p_m2, p_m4);
    // 6. linear + relu + layernorm
    k_final<<<256, 256>>>(W, bias, gamma, beta, out);
}

// round 17
// speedup vs baseline: 1.3580x; 1.2338x over previous
#include <cuda_runtime.h>
#include <cuda_bf16.h>
#include <cstdint>
#include <math.h>

// Problem constants
#define NN 32768
#define EE 8192
#define DD 128

// Scratch (static __device__ arrays — allocation-free per harness rules)
__device__ float g_dv[NN];                 // node degrees
__device__ float g_de[EE];                 // hyperedge degrees
__device__ float g_s[NN];                  // dv_inv_sqrt (written by k_deg)
__device__ __nv_bfloat16 g_hb[(size_t)NN * EE];  // bf16(H) (written by k_deg)
__device__ __nv_bfloat16 g_m1b[NN * DD];   // m1T [128 d][32768 n] = bf16(s .* x)^T
__device__ float g_m2[EE * DD];            // m2T [128 d][8192 e] fp32 (split-K acc)
__device__ __nv_bfloat16 g_m2b[EE * DD];   // bf16(m2T * dei)  (GEMM2 B operand)
__device__ float g_m4[NN * DD];            // m4 [32768 v][128 d] = H @ m3T^T

// ---------------------------------------------------------------------------
// helpers
// ---------------------------------------------------------------------------
__device__ __forceinline__ void mma16(float* c, const unsigned* a, const unsigned* b) {
    asm volatile(
        "mma.sync.aligned.m16n8k16.row.col.f32.bf16.bf16.f32 "
        "{%0,%1,%2,%3}, {%4,%5,%6,%7}, {%8,%9}, {%0,%1,%2,%3};\n"
        : "+f"(c[0]), "+f"(c[1]), "+f"(c[2]), "+f"(c[3])
        : "r"(a[0]), "r"(a[1]), "r"(a[2]), "r"(a[3]), "r"(b[0]), "r"(b[1]));
}

__device__ __forceinline__ void cp16(unsigned dst, const void* src) {
    asm volatile("cp.async.cg.shared.global [%0], [%1], 16;\n" :: "r"(dst), "l"(src));
}
__device__ __forceinline__ void cp_commit() { asm volatile("cp.async.commit_group;\n"); }
template <int N>
__device__ __forceinline__ void cp_wait() {
    asm volatile("cp.async.wait_group %0;\n" :: "n"(N) : "memory");
}

__device__ __forceinline__ void ldsm4(unsigned& r0, unsigned& r1, unsigned& r2,
                                      unsigned& r3, unsigned addr) {
    asm volatile("ldmatrix.sync.aligned.m8n8.x4.shared.b16 {%0,%1,%2,%3}, [%4];"
                 : "=r"(r0), "=r"(r1), "=r"(r2), "=r"(r3) : "r"(addr));
}
__device__ __forceinline__ void ldsm4t(unsigned& r0, unsigned& r1, unsigned& r2,
                                       unsigned& r3, unsigned addr) {
    asm volatile("ldmatrix.sync.aligned.m8n8.x4.trans.shared.b16 {%0,%1,%2,%3}, [%4];"
                 : "=r"(r0), "=r"(r1), "=r"(r2), "=r"(r3) : "r"(addr));
}

// ---------------------------------------------------------------------------
// Kernel 0: zero d_e and m2T (m2T receives split-K atomic adds)
// ---------------------------------------------------------------------------
__global__ void k_zero() {
    int i = blockIdx.x * 256 + threadIdx.x;
    float4 z = make_float4(0.f, 0.f, 0.f, 0.f);
    if (i < EE * DD / 4) reinterpret_cast<float4*>(g_m2)[i] = z;
    if (i < EE) g_de[i] = 0.0f;
}

// ---------------------------------------------------------------------------
// Kernel 1: one coalesced pass over H -> d_v (+ g_s), d_e, AND Hb = bf16(H).
// (r16-validated coalesced access; added bf16 conversion stores, 8B/thread.)
// ---------------------------------------------------------------------------
#define DEG_ROWS 128
__global__ __launch_bounds__(256) void k_deg(const float* __restrict__ H) {
    __shared__ float rowacc[DEG_ROWS];
    const int t = threadIdx.x;
    if (t < DEG_ROWS) rowacc[t] = 0.0f;
    __syncthreads();

    const int r0 = blockIdx.x * DEG_ROWS;
    float col[32];
#pragma unroll
    for (int j = 0; j < 32; j++) col[j] = 0.0f;

    const float4* H4 = reinterpret_cast<const float4*>(H);
    for (int rb = 0; rb < DEG_ROWS; rb += 4) {
        float rs0 = 0.f, rs1 = 0.f, rs2 = 0.f, rs3 = 0.f;
#pragma unroll
        for (int rr = 0; rr < 4; rr++) {
            const int row = r0 + rb + rr;
            const float4* rp = H4 + (size_t)row * (EE / 4);
            uint2* hbp = reinterpret_cast<uint2*>(g_hb + (size_t)row * EE);
            float rs = 0.0f;
#pragma unroll
            for (int j = 0; j < 8; j++) {
                float4 v = rp[j * 256 + t];           // coalesced across lanes
                col[j * 4 + 0] += v.x;
                col[j * 4 + 1] += v.y;
                col[j * 4 + 2] += v.z;
                col[j * 4 + 3] += v.w;
                rs += (v.x + v.y) + (v.z + v.w);
                __nv_bfloat162 p0 = __float22bfloat162_rn(make_float2(v.x, v.y));
                __nv_bfloat162 p1 = __float22bfloat162_rn(make_float2(v.z, v.w));
                uint2 u;
                u.x = *reinterpret_cast<unsigned*>(&p0);
                u.y = *reinterpret_cast<unsigned*>(&p1);
                hbp[j * 256 + t] = u;                 // coalesced 8B stores
            }
            if (rr == 0) rs0 = rs;
            else if (rr == 1) rs1 = rs;
            else if (rr == 2) rs2 = rs;
            else rs3 = rs;
        }
#pragma unroll
        for (int o = 16; o > 0; o >>= 1) {
            rs0 += __shfl_xor_sync(0xffffffffu, rs0, o);
            rs1 += __shfl_xor_sync(0xffffffffu, rs1, o);
            rs2 += __shfl_xor_sync(0xffffffffu, rs2, o);
            rs3 += __shfl_xor_sync(0xffffffffu, rs3, o);
        }
        if ((t & 31) == 0) {
            atomicAdd(&rowacc[rb + 0], rs0);
            atomicAdd(&rowacc[rb + 1], rs1);
            atomicAdd(&rowacc[rb + 2], rs2);
            atomicAdd(&rowacc[rb + 3], rs3);
        }
    }
    __syncthreads();
    if (t < DEG_ROWS) {
        float dv = rowacc[t];
        g_dv[r0 + t] = dv;
        g_s[r0 + t] = 1.0f / (sqrtf(dv) + 1e-8f);
    }

#pragma unroll
    for (int j = 0; j < 8; j++) {
#pragma unroll
        for (int c = 0; c < 4; c++)
            atomicAdd(&g_de[(j * 256 + t) * 4 + c], col[j * 4 + c]);
    }
}

// ---------------------------------------------------------------------------
// Kernel 2: m1b[d, n] = bf16(s[n] * x[n, d]) — tiled 32x32 transpose
// ---------------------------------------------------------------------------
__global__ __launch_bounds__(256) void k_m1t(const float* __restrict__ x) {
    __shared__ float tile[32][33];
    const int tx = threadIdx.x & 31, ty = threadIdx.x >> 5;
    const int n0 = blockIdx.x * 32, d0 = blockIdx.y * 32;
#pragma unroll
    for (int j = 0; j < 4; j++) {
        int n = n0 + ty + j * 8;
        tile[ty + j * 8][tx] = g_s[n] * x[(size_t)n * DD + d0 + tx];
    }
    __syncthreads();
#pragma unroll
    for (int j = 0; j < 4; j++) {
        int d = d0 + ty + j * 8;
        g_m1b[(size_t)d * NN + n0 + tx] = __float2bfloat16(tile[tx][ty + j * 8]);
    }
}

// ---------------------------------------------------------------------------
// Kernel 4: m2b = bf16(m2T / (d_e[e]+eps))  (e = fast dim)
// ---------------------------------------------------------------------------
__global__ void k_scale() {
    int i = blockIdx.x * 256 + threadIdx.x;
    if (i < EE * DD) {
        float dei = 1.0f / (g_de[i & (EE - 1)] + 1e-8f);
        g_m2b[i] = __float2bfloat16(g_m2[i] * dei);
    }
}

// ---------------------------------------------------------------------------
// GEMM1 (bf16 m16n8k16): m2T[d, e-tile] += sum_n m1b[d, n] * Hb[n, e]
//   A smem: [m=d 128][64B k-chunk], stride 80B  -> ldsm4 fragments
//   B smem: [k=n 32][256B e], stride 272B       -> ldsm4.trans fragments
//   Warp tile 32x64 (4m x 2n). 3-stage cp.async pipeline, wait_group 1.
//   Per warp-iter: 4 A-LDSM + 8 B-LDSM + 32 mma  (was 8 LDSM + 64 LDS + 64).
// ---------------------------------------------------------------------------
__global__ __launch_bounds__(256, 2) void k_gemm1(const __nv_bfloat16* __restrict__ hb,
                                                  const __nv_bfloat16* __restrict__ m1b,
                                                  float* __restrict__ m2t) {
    extern __shared__ __align__(16) char sm[];
    constexpr int ABY = 128 * 80;    // 10240 B
    constexpr int BBY = 32 * 272;    // 8704 B
    constexpr int STG = ABY + BBY;   // 18944 B / stage

    const int t = threadIdx.x;
    const int lane = t & 31;
    const int w = t >> 5;
    const int wm = w & 3;
    const int wn = w >> 2;
    const int e0 = blockIdx.x * 128;
    const int kb = blockIdx.y * (NN / 4);
    const unsigned sbase = (unsigned)__cvta_generic_to_shared(sm);

    float acc[2][8][4];
#pragma unroll
    for (int mt = 0; mt < 2; mt++)
#pragma unroll
        for (int nt = 0; nt < 8; nt++)
#pragma unroll
            for (int i = 0; i < 4; i++) acc[mt][nt][i] = 0.0f;

    auto issue = [&](int kt) {
        const unsigned ab = sbase + (unsigned)((kt % 3) * STG);
        const unsigned bb = ab + ABY;
        const int n0 = kb + kt * 32;
#pragma unroll
        for (int i = 0; i < 2; i++) {            // A: 128 d-rows x 4 16B-chunks
            int c = t + i * 256;
            int r = c >> 2, q = c & 3;
            cp16(ab + (unsigned)(r * 80 + q * 16),
                 (const char*)m1b + (size_t)r * (NN * 2) + (size_t)n0 * 2 + q * 16);
        }
#pragma unroll
        for (int i = 0; i < 2; i++) {            // B: 32 n-rows x 16 16B-chunks
            int c = t + i * 256;
            int r = c >> 4, q = c & 15;
            cp16(bb + (unsigned)(r * 272 + q * 16),
                 (const char*)hb + (size_t)(n0 + r) * (EE * 2) + (size_t)e0 * 2 + q * 16);
        }
        cp_commit();
    };

    issue(0);
    issue(1);

    const int iters = (NN / 4) / 32;             // 256
    const int gid = lane >> 2, tig = lane & 3;
    const int lrow = lane & 7;
    const int lmh = (lane >> 3) & 1;             // +8 rows for tiles 1,3
    const int lk16 = ((lane >> 4) & 1) * 16;     // +16B (k+8) for tiles 2,3
    const int bk8 = ((lane >> 3) & 1) * 8;       // B trans: +8 k-rows (b1 tiles)
    const int be16 = ((lane >> 4) & 1) * 16;     // B trans: +8 e cols (16B)

    for (int kt = 0; kt < iters; kt++) {
        cp_wait<1>();
        __syncthreads();
        if (kt + 2 < iters) issue(kt + 2);

        const unsigned ab = sbase + (unsigned)((kt % 3) * STG);
        const unsigned bb = ab + ABY;
#pragma unroll
        for (int ks = 0; ks < 2; ks++) {         // two k16 steps per 32-K iter
            const int kB = ks * 32;              // A byte offset (16 bf16)
            const int kR = ks * 16;              // B k-row base
            unsigned af[2][4];
#pragma unroll
            for (int mt = 0; mt < 2; mt++) {
                int m = wm * 32 + mt * 16 + lmh * 8 + lrow;
                ldsm4(af[mt][0], af[mt][1], af[mt][2], af[mt][3],
                      ab + (unsigned)(m * 80 + kB + lk16));
            }
            unsigned bf[8][2];
#pragma unroll
            for (int pe = 0; pe < 4; pe++) {     // 4 trans-LDSM cover 64 e
                int krow = kR + bk8 + lrow;
                int ebyte = (wn * 64 + pe * 16) * 2 + be16;
                unsigned r0, r1, r2, r3;
                ldsm4t(r0, r1, r2, r3, bb + (unsigned)(krow * 272 + ebyte));
                bf[2 * pe][0] = r0;
                bf[2 * pe][1] = r1;
                bf[2 * pe + 1][0] = r2;
                bf[2 * pe + 1][1] = r3;
            }
#pragma unroll
            for (int mt = 0; mt < 2; mt++)
#pragma unroll
                for (int nt = 0; nt < 8; nt++) mma16(acc[mt][nt], af[mt], bf[nt]);
        }
    }

    // Epilogue: D[m=d][n=e]; c0:(g,2t) c1:(g,2t+1) c2:(g+8,2t) c3:(g+8,2t+1)
#pragma unroll
    for (int mt = 0; mt < 2; mt++) {
#pragma unroll
        for (int nt = 0; nt < 8; nt++) {
            int d = wm * 32 + mt * 16 + gid;
            int e = e0 + wn * 64 + nt * 8 + 2 * tig;
            float* p = m2t + (size_t)d * EE + e;
            atomicAdd(p, acc[mt][nt][0]);
            atomicAdd(p + 1, acc[mt][nt][1]);
            atomicAdd(p + 8 * EE, acc[mt][nt][2]);
            atomicAdd(p + 8 * EE + 1, acc[mt][nt][3]);
        }
    }
}

// ---------------------------------------------------------------------------
// GEMM2 (bf16 m16n8k16): m4[v-tile, d] = sum_e Hb[v, e] * m2b[d, e]
//   A smem: [m=v 128][64B e-chunk], stride 80B -> ldsm4
//   B smem: [n=d 128][64B e-chunk], stride 80B -> ldsm4 (non-trans, [n][k])
//   Warp tile 32x64. 3-stage pipeline.
// ---------------------------------------------------------------------------
__global__ __launch_bounds__(256, 2) void k_gemm2(const __nv_bfloat16* __restrict__ hb,
                                                  const __nv_bfloat16* __restrict__ m3b,
                                                  float* __restrict__ m4) {
    extern __shared__ __align__(16) char sm[];
    constexpr int ABY = 128 * 80;
    constexpr int BBY = 128 * 80;
    constexpr int STG = ABY + BBY;               // 20480 B / stage

    const int t = threadIdx.x;
    const int lane = t & 31;
    const int w = t >> 5;
    const int wm = w & 3;
    const int wn = w >> 2;
    const int v0 = blockIdx.x * 128;
    const unsigned sbase = (unsigned)__cvta_generic_to_shared(sm);

    float acc[2][8][4];
#pragma unroll
    for (int mt = 0; mt < 2; mt++)
#pragma unroll
        for (int nt = 0; nt < 8; nt++)
#pragma unroll
            for (int i = 0; i < 4; i++) acc[mt][nt][i] = 0.0f;

    auto issue = [&](int kt) {
        const unsigned ab = sbase + (unsigned)((kt % 3) * STG);
        const unsigned bb = ab + ABY;
        const int ke = kt * 32;
#pragma unroll
        for (int i = 0; i < 2; i++) {            // A: Hb 128 v-rows x 4 chunks
            int c = t + i * 256;
            int r = c >> 2, q = c & 3;
            cp16(ab + (unsigned)(r * 80 + q * 16),
                 (const char*)hb + (size_t)(v0 + r) * (EE * 2) + (size_t)ke * 2 + q * 16);
        }
#pragma unroll
        for (int i = 0; i < 2; i++) {            // B: m3b 128 d-rows x 4 chunks
            int c = t + i * 256;
            int r = c >> 2, q = c & 3;
            cp16(bb + (unsigned)(r * 80 + q * 16),
                 (const char*)m3b + (size_t)r * (EE * 2) + (size_t)ke * 2 + q * 16);
        }
        cp_commit();
    };

    issue(0);
    issue(1);

    const int iters = EE / 32;                    // 256
    const int gid = lane >> 2, tig = lane & 3;
    const int lrow = lane & 7;
    const int lmh = (lane >> 3) & 1;
    const int lk16 = ((lane >> 4) & 1) * 16;
    const int bn8 = ((lane >> 4) & 1) * 8;        // B: +8 n-rows for tiles 2,3
    const int bk16 = ((lane >> 3) & 1) * 16;      // B: +16B (k+8) for tiles 1,3

    for (int kt = 0; kt < iters; kt++) {
        cp_wait<1>();
        __syncthreads();
        if (kt + 2 < iters) issue(kt + 2);

        const unsigned ab = sbase + (unsigned)((kt % 3) * STG);
        const unsigned bb = ab + ABY;
#pragma unroll
        for (int ks = 0; ks < 2; ks++) {
            const int kB = ks * 32;
            unsigned af[2][4];
#pragma unroll
            for (int mt = 0; mt < 2; mt++) {
                int m = wm * 32 + mt * 16 + lmh * 8 + lrow;
                ldsm4(af[mt][0], af[mt][1], af[mt][2], af[mt][3],
                      ab + (unsigned)(m * 80 + kB + lk16));
            }
            unsigned bf[8][2];
#pragma unroll
            for (int pe = 0; pe < 4; pe++) {
                int n = wn * 64 + pe * 16 + bn8 + lrow;
                unsigned r0, r1, r2, r3;
                ldsm4(r0, r1, r2, r3, bb + (unsigned)(n * 80 + kB + bk16));
                bf[2 * pe][0] = r0;
                bf[2 * pe][1] = r1;
                bf[2 * pe + 1][0] = r2;
                bf[2 * pe + 1][1] = r3;
            }
#pragma unroll
            for (int mt = 0; mt < 2; mt++)
#pragma unroll
                for (int nt = 0; nt < 8; nt++) mma16(acc[mt][nt], af[mt], bf[nt]);
        }
    }

    // Epilogue: D[m=v][n=d] plain store
#pragma unroll
    for (int mt = 0; mt < 2; mt++) {
#pragma unroll
        for (int nt = 0; nt < 8; nt++) {
            int m = v0 + wm * 32 + mt * 16 + gid;
            int n = wn * 64 + nt * 8 + 2 * tig;
            float* p = m4 + (size_t)m * DD + n;
            p[0] = acc[mt][nt][0];
            p[1] = acc[mt][nt][1];
            p[8 * DD] = acc[mt][nt][2];
            p[8 * DD + 1] = acc[mt][nt][3];
        }
    }
}

// ---------------------------------------------------------------------------
// Kernel 6: per row n:  v = s[n]*m4[n,:];  h = W@v + b;  relu;  layernorm.
// ---------------------------------------------------------------------------
__global__ __launch_bounds__(256) void k_final(const float* __restrict__ W,
                                               const float* __restrict__ bias,
                                               const float* __restrict__ gamma,
                                               const float* __restrict__ beta,
                                               float* __restrict__ out) {
    __shared__ float vbuf[8][132];
    const int t = threadIdx.x;
    const int lane = t & 31;
    const int w = t >> 5;

    const float4 bb = *reinterpret_cast<const float4*>(bias + 4 * lane);
    const float4 gg = *reinterpret_cast<const float4*>(gamma + 4 * lane);
    const float4 eb = *reinterpret_cast<const float4*>(beta + 4 * lane);
    const float4* W4 = reinterpret_cast<const float4*>(W);

    for (int n = blockIdx.x * 8 + w; n < NN; n += gridDim.x * 8) {
        const float s = g_s[n];
        float4 mv = *reinterpret_cast<const float4*>(g_m4 + (size_t)n * DD + 4 * lane);
        vbuf[w][4 * lane + 0] = s * mv.x;
        vbuf[w][4 * lane + 1] = s * mv.y;
        vbuf[w][4 * lane + 2] = s * mv.z;
        vbuf[w][4 * lane + 3] = s * mv.w;
        __syncwarp();

        float h0 = bb.x, h1 = bb.y, h2 = bb.z, h3 = bb.w;
#pragma unroll 8
        for (int dq = 0; dq < 32; dq++) {
            float4 v4 = *reinterpret_cast<float4*>(&vbuf[w][dq * 4]);
            float4 w0 = W4[(4 * lane + 0) * 32 + dq];
            float4 w1 = W4[(4 * lane + 1) * 32 + dq];
            float4 w2 = W4[(4 * lane + 2) * 32 + dq];
            float4 w3 = W4[(4 * lane + 3) * 32 + dq];
            h0 += w0.x * v4.x + w0.y * v4.y + w0.z * v4.z + w0.w * v4.w;
            h1 += w1.x * v4.x + w1.y * v4.y + w1.z * v4.z + w1.w * v4.w;
            h2 += w2.x * v4.x + w2.y * v4.y + w2.z * v4.z + w2.w * v4.w;
            h3 += w3.x * v4.x + w3.y * v4.y + w3.z * v4.z + w3.w * v4.w;
        }
        h0 = fmaxf(h0, 0.0f);
        h1 = fmaxf(h1, 0.0f);
        h2 = fmaxf(h2, 0.0f);
        h3 = fmaxf(h3, 0.0f);

        float sum = h0 + h1 + h2 + h3;
#pragma unroll
        for (int o = 16; o > 0; o >>= 1) sum += __shfl_xor_sync(0xffffffffu, sum, o);
        const float mu = sum * (1.0f / 128.0f);
        const float d0 = h0 - mu, d1 = h1 - mu, d2 = h2 - mu, d3 = h3 - mu;
        float vs = d0 * d0 + d1 * d1 + d2 * d2 + d3 * d3;
#pragma unroll
        for (int o = 16; o > 0; o >>= 1) vs += __shfl_xor_sync(0xffffffffu, vs, o);
        const float inv = rsqrtf(vs * (1.0f / 128.0f) + 1e-5f);

        float4 o4;
        o4.x = gg.x * d0 * inv + eb.x;
        o4.y = gg.y * d1 * inv + eb.y;
        o4.z = gg.z * d2 * inv + eb.z;
        o4.w = gg.w * d3 * inv + eb.w;
        *reinterpret_cast<float4*>(out + (size_t)n * DD + 4 * lane) = o4;
        __syncwarp();
    }
}

// ---------------------------------------------------------------------------
// Launch
// ---------------------------------------------------------------------------
extern "C" void kernel_launch(void* const* d_in, const int* in_sizes, int n_in,
                              void* d_out, int out_size) {
    const float* x     = (const float*)d_in[0];   // (N, 128)
    const float* H     = (const float*)d_in[1];   // (N, E)
    const float* W     = (const float*)d_in[2];   // (128, 128)
    const float* bias  = (const float*)d_in[3];   // (128,)
    const float* gamma = (const float*)d_in[4];   // (128,)
    const float* beta  = (const float*)d_in[5];   // (128,)
    float* out = (float*)d_out;

    // Resolve true device addresses of scratch symbols (round-8 fix).
    __nv_bfloat16 *p_hb = nullptr, *p_m1b = nullptr, *p_m2b = nullptr;
    float *p_m2 = nullptr, *p_m4 = nullptr;
    cudaGetSymbolAddress((void**)&p_hb, g_hb);
    cudaGetSymbolAddress((void**)&p_m1b, g_m1b);
    cudaGetSymbolAddress((void**)&p_m2b, g_m2b);
    cudaGetSymbolAddress((void**)&p_m2, g_m2);
    cudaGetSymbolAddress((void**)&p_m4, g_m4);

    constexpr int SMEM_G1 = 3 * (128 * 80 + 32 * 272);    // 56832 B
    constexpr int SMEM_G2 = 3 * (128 * 80 + 128 * 80);    // 61440 B
    cudaFuncSetAttribute(k_gemm1, cudaFuncAttributeMaxDynamicSharedMemorySize, SMEM_G1);
    cudaFuncSetAttribute(k_gemm2, cudaFuncAttributeMaxDynamicSharedMemorySize, SMEM_G2);

    // 0. zero d_e + m2T (split-K accumulator)
    k_zero<<<(EE * DD / 4 + 255) / 256, 256>>>();
    // 1. degrees + Hb = bf16(H) (single coalesced pass over H); writes g_s
    k_deg<<<NN / DEG_ROWS, 256>>>(H);
    // 2. m1b = bf16(s .* x)^T
    k_m1t<<<dim3(NN / 32, DD / 32), 256>>>(x);
    // 3. GEMM1: m2T += m1b @ Hb   (split-K=4, atomic)  <- profiled launch
    k_gemm1<<<dim3(EE / 128, 4), 256, SMEM_G1>>>(p_hb, p_m1b, p_m2);
    // 4. m2b = bf16(m2T / (d_e+eps))
    k_scale<<<(EE * DD) / 256, 256>>>();
    // 5. GEMM2: m4 = Hb @ m2b^T
    k_gemm2<<<NN / 128, 256, SMEM_G2>>>(p_hb, p_m2b, p_m4);
    // 6. linear + relu + layernorm
    k_final<<<256, 256>>>(W, bias, gamma, beta, out);
}